// round 10
// baseline (speedup 1.0000x reference)
#include <cuda_runtime.h>
#include <cuda_bf16.h>
#include <cstdint>

// Problem shape (fixed for this instance)
#define B_    16
#define N_    4096
#define S_    1024
#define C2_   256
#define C1_   128
#define CIN_  384      // C2_ + C1_
#define M1_   256
#define M2_   128
#define MROWS (B_ * N_)   // 65536

// ---------------------------------------------------------------------------
// Scratch (static __device__ globals)
// ---------------------------------------------------------------------------
__device__ __nv_bfloat16 g_xh[(size_t)MROWS * CIN_];  // concat input hi plane
__device__ __nv_bfloat16 g_xl[(size_t)MROWS * CIN_];  // concat input lo plane
__device__ float g_y1[(size_t)MROWS * M1_];           // raw conv1 output fp32
__device__ __nv_bfloat16 g_w1h[M1_ * CIN_], g_w1l[M1_ * CIN_];
__device__ __nv_bfloat16 g_w2h[M2_ * M1_],  g_w2l[M2_ * M1_];
__device__ float g_sum1[M1_], g_sq1[M1_];
__device__ float g_sum2[M2_], g_sq2[M2_];

// ---------------------------------------------------------------------------
// PTX helpers — all baseline compute_80-level (no arch-specific features)
// ---------------------------------------------------------------------------
__device__ __forceinline__ unsigned smem_u32(const void* p) {
    unsigned a;
    asm("{ .reg .u64 t; cvta.to.shared.u64 t, %1; cvt.u32.u64 %0, t; }"
        : "=r"(a) : "l"(p));
    return a;
}
__device__ __forceinline__ void cp16(unsigned dst, const void* src) {
    asm volatile("cp.async.cg.shared.global [%0], [%1], 16;"
                 :: "r"(dst), "l"(src) : "memory");
}
__device__ __forceinline__ void cp_commit() {
    asm volatile("cp.async.commit_group;" ::: "memory");
}
__device__ __forceinline__ void cp_wait_all() {
    asm volatile("cp.async.wait_group 0;" ::: "memory");
}
__device__ __forceinline__ void ldsm4(unsigned* r, unsigned addr) {
    asm volatile("ldmatrix.sync.aligned.m8n8.x4.shared.b16 {%0,%1,%2,%3}, [%4];"
                 : "=r"(r[0]), "=r"(r[1]), "=r"(r[2]), "=r"(r[3]) : "r"(addr));
}
__device__ __forceinline__ void mma16816(float* d, const unsigned* a,
                                         unsigned b0, unsigned b1) {
    asm volatile(
        "mma.sync.aligned.m16n8k16.row.col.f32.bf16.bf16.f32 "
        "{%0,%1,%2,%3}, {%4,%5,%6,%7}, {%8,%9}, {%0,%1,%2,%3};"
        : "+f"(d[0]), "+f"(d[1]), "+f"(d[2]), "+f"(d[3])
        : "r"(a[0]), "r"(a[1]), "r"(a[2]), "r"(a[3]), "r"(b0), "r"(b1));
}
__device__ __forceinline__ unsigned pack2(__nv_bfloat16 lo, __nv_bfloat16 hi) {
    return ((unsigned)__bfloat16_as_ushort(hi) << 16) |
           (unsigned)__bfloat16_as_ushort(lo);
}

// ---------------------------------------------------------------------------
// prep_a: split W1 into bf16 hi/lo planes        (launch index 0)
// prep_b: split W2 + zero BN stat accumulators   (launch index 1)
// ---------------------------------------------------------------------------
__global__ void prep_a_kernel(const float* __restrict__ W1) {
    const int idx = blockIdx.x * 256 + threadIdx.x;
    if (idx < M1_ * CIN_) {
        float w = W1[idx];
        __nv_bfloat16 h = __float2bfloat16(w);
        g_w1h[idx] = h;
        g_w1l[idx] = __float2bfloat16(w - __bfloat162float(h));
    }
}
__global__ void prep_b_kernel(const float* __restrict__ W2) {
    const int idx = blockIdx.x * 256 + threadIdx.x;
    if (blockIdx.x == 0) {
        const int t = threadIdx.x;
        if (t < M1_) { g_sum1[t] = 0.f; g_sq1[t] = 0.f; }
        if (t < M2_) { g_sum2[t] = 0.f; g_sq2[t] = 0.f; }
    }
    if (idx < M2_ * M1_) {
        float w = W2[idx];
        __nv_bfloat16 h = __float2bfloat16(w);
        g_w2h[idx] = h;
        g_w2l[idx] = __float2bfloat16(w - __bfloat162float(h));
    }
}

// ---------------------------------------------------------------------------
// Kernel: 3-NN interpolation + concat -> split bf16 planes g_xh/g_xl
// ---------------------------------------------------------------------------
__global__ void interp_concat_kernel(const float* __restrict__ txyz,
                                     const float* __restrict__ sxyz,
                                     const float* __restrict__ sfeat,
                                     const float* __restrict__ skip)
{
    __shared__ float4 s_src[S_];
    __shared__ float  s_w[3][128];
    __shared__ int    s_i[3][128];

    const int b   = blockIdx.y;
    const int p0  = blockIdx.x * 128;
    const int tid = threadIdx.x;

    const float* sx = sxyz + (size_t)b * S_ * 3;
    for (int i = tid; i < S_; i += 128) {
        float x = sx[i * 3 + 0], y = sx[i * 3 + 1], z = sx[i * 3 + 2];
        s_src[i] = make_float4(x, y, z, x * x + y * y + z * z);
    }
    __syncthreads();

    const int n = p0 + tid;
    const float* tp = txyz + ((size_t)b * N_ + n) * 3;
    const float tx0 = tp[0], ty0 = tp[1], tz0 = tp[2];
    const float q2 = tx0 * tx0 + ty0 * ty0 + tz0 * tz0;

    float d0 = 3.4e38f, d1 = 3.4e38f, d2 = 3.4e38f;
    int   i0 = 0, i1 = 0, i2 = 0;
    #pragma unroll 4
    for (int s = 0; s < S_; ++s) {
        float4 v = s_src[s];
        float cr   = tx0 * v.x + ty0 * v.y + tz0 * v.z;
        float dist = fmaxf(q2 + v.w - 2.f * cr, 0.f);
        if (dist < d2) {
            if (dist < d1) {
                d2 = d1; i2 = i1;
                if (dist < d0) { d1 = d0; i1 = i0; d0 = dist; i0 = s; }
                else           { d1 = dist; i1 = s; }
            } else { d2 = dist; i2 = s; }
        }
    }

    int   ii[3] = { i0, i1, i2 };
    float w[3];
    float wsum = 0.f;
    #pragma unroll
    for (int k = 0; k < 3; ++k) {
        float4 v = s_src[ii[k]];
        float dx = tx0 - v.x, dy = ty0 - v.y, dz = tz0 - v.z;
        float dd = dx * dx + dy * dy + dz * dz;
        w[k] = 1.f / (dd + 1e-8f);
        wsum += w[k];
    }
    float inv = 1.f / wsum;
    #pragma unroll
    for (int k = 0; k < 3; ++k) { s_w[k][tid] = w[k] * inv; s_i[k][tid] = ii[k]; }
    __syncthreads();

    const float* F = sfeat + (size_t)b * S_ * C2_;
    for (int p = 0; p < 128; ++p) {
        const float w0 = s_w[0][p], w1 = s_w[1][p], w2 = s_w[2][p];
        const float* f0 = F + (size_t)s_i[0][p] * C2_;
        const float* f1 = F + (size_t)s_i[1][p] * C2_;
        const float* f2 = F + (size_t)s_i[2][p] * C2_;
        const size_t row = (size_t)b * N_ + p0 + p;
        __nv_bfloat162* xh2 = (__nv_bfloat162*)(g_xh + row * CIN_);
        __nv_bfloat162* xl2 = (__nv_bfloat162*)(g_xl + row * CIN_);

        {   // interp channels: pair q = tid covers channels 2q, 2q+1 (0..255)
            const int q = tid;
            float2 a = *(const float2*)(f0 + 2 * q);
            float2 b2 = *(const float2*)(f1 + 2 * q);
            float2 c = *(const float2*)(f2 + 2 * q);
            float v0 = w0 * a.x + w1 * b2.x + w2 * c.x;
            float v1 = w0 * a.y + w1 * b2.y + w2 * c.y;
            __nv_bfloat16 h0 = __float2bfloat16(v0);
            __nv_bfloat16 h1 = __float2bfloat16(v1);
            __nv_bfloat162 hh; hh.x = h0; hh.y = h1;
            __nv_bfloat162 ll;
            ll.x = __float2bfloat16(v0 - __bfloat162float(h0));
            ll.y = __float2bfloat16(v1 - __bfloat162float(h1));
            xh2[q] = hh; xl2[q] = ll;
        }
        if (tid < 64) {  // skip channels: pairs 128..191
            const int q = 128 + tid;
            float2 sv = *(const float2*)(skip + row * C1_ + 2 * tid);
            __nv_bfloat16 h0 = __float2bfloat16(sv.x);
            __nv_bfloat16 h1 = __float2bfloat16(sv.y);
            __nv_bfloat162 hh; hh.x = h0; hh.y = h1;
            __nv_bfloat162 ll;
            ll.x = __float2bfloat16(sv.x - __bfloat162float(h0));
            ll.y = __float2bfloat16(sv.y - __bfloat162float(h1));
            xh2[q] = hh; xl2[q] = ll;
        }
    }
}

// ---------------------------------------------------------------------------
// mma.sync GEMM: C[M, NOUT_tile=128] = T(A)[M, K] * W^T   (split-bf16, 3 HMMA/k16)
//   FIRST : MTILE=128, A = (g_xh,g_xl) via cp.async; C = g_y1; stats1
//   SECOND: MTILE=64,  A = g_y1 fp32 -> BN1+ReLU+split in producer; C = out; stats2
// 256 thr = 8 warps (2 M x 4 N). Smem rows: 32 bf16 + 8 pad = 80 B.
// ---------------------------------------------------------------------------
template <int K, int NOUT, bool SECOND>
__global__ void __launch_bounds__(256, SECOND ? 3 : 2)
gemm_mma_kernel(float* __restrict__ outp,
                const float* __restrict__ gamma, const float* __restrict__ beta)
{
    constexpr int NC    = K / 32;
    constexpr int MTILE = SECOND ? 64 : 128;
    constexpr int APL   = MTILE * 80;          // one A plane
    constexpr int BPL   = 128 * 80;            // one B plane
    constexpr int STAGE = 2 * APL + 2 * BPL;
    constexpr int REDO  = 2 * STAGE;
    constexpr int SCO   = REDO + 1024;
    constexpr int ITER  = MTILE / 32;          // acc i-range (4 or 2)

    extern __shared__ char sm[];
    const unsigned sb = smem_u32(sm);

    const int tid  = threadIdx.x;
    const int wid  = tid >> 5;
    const int lane = tid & 31;
    const int warpM = wid & 1;
    const int warpN = wid >> 1;
    const int n0 = blockIdx.x * 128;
    const size_t m0 = (size_t)blockIdx.y * MTILE;

    float* C    = SECOND ? outp : g_y1;
    const __nv_bfloat16* Wh = SECOND ? g_w2h : g_w1h;
    const __nv_bfloat16* Wl = SECOND ? g_w2l : g_w1l;
    float* gsum = SECOND ? g_sum2 : g_sum1;
    float* gsq  = SECOND ? g_sq2  : g_sq1;

    float* redsum = (float*)(sm + REDO);
    float* redsq  = redsum + 128;
    float* s_sc   = (float*)(sm + SCO);
    float* s_sh   = s_sc + K;

    if (tid < 128) { redsum[tid] = 0.f; redsq[tid] = 0.f; }
    if (SECOND && tid < K) {             // BN1 coefficients from raw sums
        const float invC = 1.0f / (float)MROWS;
        float mean = g_sum1[tid] * invC;
        float var  = g_sq1[tid] * invC - mean * mean;
        float sc   = gamma[tid] * rsqrtf(var + 1e-5f);
        s_sc[tid] = sc;
        s_sh[tid] = fmaf(-mean, sc, beta[tid]);
    }
    __syncthreads();

    // ---- producers -------------------------------------------------------
    auto produceB = [&](int buf, int kc) {
        const int r = tid >> 2, c = tid & 3;
        const unsigned bh = sb + buf * STAGE + 2 * APL;
        #pragma unroll
        for (int s = 0; s < 2; ++s) {
            const int row = r + 64 * s;
            const size_t g = (size_t)(n0 + row) * K + kc * 32 + c * 8;
            const unsigned d = bh + row * 80 + c * 16;
            cp16(d,       Wh + g);
            cp16(d + BPL, Wl + g);
        }
    };
    auto produceA1 = [&](int buf, int kc) {       // FIRST: cp.async bf16 planes
        const int r = tid >> 2, c = tid & 3;
        const unsigned ah = sb + buf * STAGE;
        #pragma unroll
        for (int s = 0; s < 2; ++s) {
            const int row = r + 64 * s;
            const size_t g = (m0 + row) * CIN_ + kc * 32 + c * 8;
            const unsigned d = ah + row * 80 + c * 16;
            cp16(d,       g_xh + g);
            cp16(d + APL, g_xl + g);
        }
    };
    // SECOND (MTILE=64): 64 rows x 32 floats, 256 thr -> 8 floats each
    float4 areg[2];
    auto ldA2 = [&](int kc) {
        const int r = tid >> 2, q4 = tid & 3;
        const float* src = g_y1 + (m0 + r) * K + kc * 32 + q4 * 8;
        areg[0] = *(const float4*)(src);
        areg[1] = *(const float4*)(src + 4);
    };
    auto stA2 = [&](int buf, int kc) {
        const int r = tid >> 2, q4 = tid & 3;
        const int kk = kc * 32 + q4 * 8;
        unsigned hi[4], lo[4];
        #pragma unroll
        for (int q = 0; q < 2; ++q) {
            float4 v = areg[q];
            const int kb = kk + q * 4;
            v.x = fmaxf(fmaf(v.x, s_sc[kb + 0], s_sh[kb + 0]), 0.f);
            v.y = fmaxf(fmaf(v.y, s_sc[kb + 1], s_sh[kb + 1]), 0.f);
            v.z = fmaxf(fmaf(v.z, s_sc[kb + 2], s_sh[kb + 2]), 0.f);
            v.w = fmaxf(fmaf(v.w, s_sc[kb + 3], s_sh[kb + 3]), 0.f);
            __nv_bfloat16 h0 = __float2bfloat16(v.x), h1 = __float2bfloat16(v.y);
            __nv_bfloat16 h2 = __float2bfloat16(v.z), h3 = __float2bfloat16(v.w);
            hi[q * 2 + 0] = pack2(h0, h1);
            hi[q * 2 + 1] = pack2(h2, h3);
            lo[q * 2 + 0] = pack2(__float2bfloat16(v.x - __bfloat162float(h0)),
                                  __float2bfloat16(v.y - __bfloat162float(h1)));
            lo[q * 2 + 1] = pack2(__float2bfloat16(v.z - __bfloat162float(h2)),
                                  __float2bfloat16(v.w - __bfloat162float(h3)));
        }
        char* ah = sm + buf * STAGE + r * 80 + q4 * 16;
        *(uint4*)(ah)       = make_uint4(hi[0], hi[1], hi[2], hi[3]);
        *(uint4*)(ah + APL) = make_uint4(lo[0], lo[1], lo[2], lo[3]);
    };

    // ---- ldmatrix per-lane base offsets ----------------------------------
    const unsigned aRowOff =
        (unsigned)((warpM * (MTILE / 2) + (lane & 15)) * 80 + ((lane >> 4) & 1) * 16);
    const unsigned bRowOff =
        (unsigned)((warpN * 32 + ((lane >> 4) << 3) + (lane & 7)) * 80 +
                   ((lane >> 3) & 1) * 16);

    float acc[ITER][4][4];
    #pragma unroll
    for (int i = 0; i < ITER; ++i)
        #pragma unroll
        for (int j = 0; j < 4; ++j)
            #pragma unroll
            for (int q = 0; q < 4; ++q) acc[i][j][q] = 0.f;

    // ---- prologue --------------------------------------------------------
    if (SECOND) { ldA2(0); stA2(0, 0); }
    else        produceA1(0, 0);
    produceB(0, 0);
    cp_commit();
    if (SECOND && NC > 1) ldA2(1);

    // ---- main loop -------------------------------------------------------
    for (int kc = 0; kc < NC; ++kc) {
        cp_wait_all();
        __syncthreads();
        const int nbuf = (kc + 1) & 1;
        if (kc + 1 < NC) {
            produceB(nbuf, kc + 1);
            if (!SECOND) produceA1(nbuf, kc + 1);
        }

        const unsigned base = sb + (kc & 1) * STAGE;
        const unsigned aH = base + aRowOff;
        const unsigned aL = aH + APL;
        const unsigned bH = base + 2 * APL + bRowOff;
        const unsigned bL = bH + BPL;

        #pragma unroll
        for (int k16 = 0; k16 < 2; ++k16) {
            const unsigned ko = k16 * 32;
            unsigned bh[8], bl[8];
            ldsm4(bh + 0, bH + ko);
            ldsm4(bh + 4, bH + ko + 16 * 80);
            ldsm4(bl + 0, bL + ko);
            ldsm4(bl + 4, bL + ko + 16 * 80);
            #pragma unroll
            for (int i = 0; i < ITER; ++i) {
                unsigned ah[4], al[4];
                ldsm4(ah, aH + ko + i * (16 * 80));
                ldsm4(al, aL + ko + i * (16 * 80));
                #pragma unroll
                for (int j = 0; j < 4; ++j)
                    mma16816(acc[i][j], ah, bh[2 * j], bh[2 * j + 1]);
                #pragma unroll
                for (int j = 0; j < 4; ++j)
                    mma16816(acc[i][j], ah, bl[2 * j], bl[2 * j + 1]);
                #pragma unroll
                for (int j = 0; j < 4; ++j)
                    mma16816(acc[i][j], al, bh[2 * j], bh[2 * j + 1]);
            }
        }

        if (SECOND && kc + 1 < NC) {
            stA2(nbuf, kc + 1);                  // LDG latency hidden by MMAs
            if (kc + 2 < NC) ldA2(kc + 2);
        }
        cp_commit();
    }

    // ---- epilogue: regs -> smem C-tile -> coalesced store + BN stats -----
    __syncthreads();                      // all tile reads done; reuse smem
    float* Ct = (float*)sm;               // MTILE x 132 fp32
    const int g = lane >> 2, q = lane & 3;
    #pragma unroll
    for (int i = 0; i < ITER; ++i) {
        const int r0 = warpM * (MTILE / 2) + i * 16 + g;
        #pragma unroll
        for (int j = 0; j < 4; ++j) {
            const int c0 = warpN * 32 + j * 8 + q * 2;
            *(float2*)&Ct[r0 * 132 + c0]       = make_float2(acc[i][j][0], acc[i][j][1]);
            *(float2*)&Ct[(r0 + 8) * 132 + c0] = make_float2(acc[i][j][2], acc[i][j][3]);
        }
    }
    __syncthreads();

    float4 s4 = make_float4(0, 0, 0, 0), q4v = make_float4(0, 0, 0, 0);
    const int cc = (tid & 31) * 4;
    #pragma unroll
    for (int p = 0; p < MTILE / 8; ++p) {
        const int idx = tid + p * 256;
        const int row = idx >> 5;
        float4 v = *(float4*)&Ct[row * 132 + cc];
        *(float4*)(C + (m0 + row) * NOUT + n0 + cc) = v;
        s4.x += v.x; s4.y += v.y; s4.z += v.z; s4.w += v.w;
        q4v.x = fmaf(v.x, v.x, q4v.x); q4v.y = fmaf(v.y, v.y, q4v.y);
        q4v.z = fmaf(v.z, v.z, q4v.z); q4v.w = fmaf(v.w, v.w, q4v.w);
    }
    atomicAdd(&redsum[cc + 0], s4.x); atomicAdd(&redsum[cc + 1], s4.y);
    atomicAdd(&redsum[cc + 2], s4.z); atomicAdd(&redsum[cc + 3], s4.w);
    atomicAdd(&redsq [cc + 0], q4v.x); atomicAdd(&redsq [cc + 1], q4v.y);
    atomicAdd(&redsq [cc + 2], q4v.z); atomicAdd(&redsq [cc + 3], q4v.w);
    __syncthreads();
    if (tid < 128) {
        atomicAdd(&gsum[n0 + tid], redsum[tid]);
        atomicAdd(&gsq [n0 + tid], redsq [tid]);
    }
}

// ---------------------------------------------------------------------------
// final BN2 + ReLU, in-place on d_out [MROWS, 128]; coefs computed per block
// ---------------------------------------------------------------------------
__global__ void bn_out_kernel(float* __restrict__ out,
                              const float* __restrict__ gamma2,
                              const float* __restrict__ beta2)
{
    __shared__ float s2[M2_], t2[M2_];
    const int tid = threadIdx.x;
    if (tid < M2_) {
        const float invC = 1.0f / (float)MROWS;
        float mean = g_sum2[tid] * invC;
        float var  = g_sq2[tid] * invC - mean * mean;
        float sc   = gamma2[tid] * rsqrtf(var + 1e-5f);
        s2[tid] = sc;
        t2[tid] = fmaf(-mean, sc, beta2[tid]);
    }
    __syncthreads();

    const size_t idx = (size_t)blockIdx.x * blockDim.x + tid;  // float4 idx
    float4 v = ((float4*)out)[idx];
    const int c = ((int)(idx * 4)) & (M2_ - 1);
    v.x = fmaxf(fmaf(v.x, s2[c + 0], t2[c + 0]), 0.f);
    v.y = fmaxf(fmaf(v.y, s2[c + 1], t2[c + 1]), 0.f);
    v.z = fmaxf(fmaf(v.z, s2[c + 2], t2[c + 2]), 0.f);
    v.w = fmaxf(fmaf(v.w, s2[c + 3], t2[c + 3]), 0.f);
    ((float4*)out)[idx] = v;
}

// ---------------------------------------------------------------------------
// Launch — GEMM1 deliberately at launch index 3 (= ncu's sampled launch)
// ---------------------------------------------------------------------------
extern "C" void kernel_launch(void* const* d_in, const int* in_sizes, int n_in,
                              void* d_out, int out_size)
{
    const float* txyz   = (const float*)d_in[0];
    const float* sxyz   = (const float*)d_in[1];
    const float* sfeat  = (const float*)d_in[2];
    const float* skip   = (const float*)d_in[3];
    const float* W1     = (const float*)d_in[4];
    const float* gamma1 = (const float*)d_in[5];
    const float* beta1  = (const float*)d_in[6];
    const float* W2     = (const float*)d_in[7];
    const float* gamma2 = (const float*)d_in[8];
    const float* beta2  = (const float*)d_in[9];
    float* out = (float*)d_out;

    // smem sizes: 2*STAGE + 1024 (+ BN coef region for SECOND)
    const int SMEM1 = 2 * (2 * 128 * 80 + 2 * 128 * 80) + 1024;                 // 82944
    const int SMEM2 = 2 * (2 * 64 * 80 + 2 * 128 * 80) + 1024 + 2 * M1_ * 4;    // 64512
    cudaFuncSetAttribute(gemm_mma_kernel<CIN_, M1_, false>,
                         cudaFuncAttributeMaxDynamicSharedMemorySize, SMEM1);
    cudaFuncSetAttribute(gemm_mma_kernel<M1_, M2_, true>,
                         cudaFuncAttributeMaxDynamicSharedMemorySize, SMEM2);

    prep_a_kernel<<<(M1_ * CIN_ + 255) / 256, 256>>>(W1);                      // 0
    prep_b_kernel<<<(M2_ * M1_ + 255) / 256, 256>>>(W2);                       // 1
    interp_concat_kernel<<<dim3(N_ / 128, B_), 128>>>(txyz, sxyz, sfeat, skip); // 2
    gemm_mma_kernel<CIN_, M1_, false><<<dim3(M1_ / 128, MROWS / 128), 256, SMEM1>>>(
        nullptr, nullptr, nullptr);                                            // 3 <- profiled
    gemm_mma_kernel<M1_, M2_, true><<<dim3(M2_ / 128, MROWS / 64), 256, SMEM2>>>(
        out, gamma1, beta1);                                                   // 4
    bn_out_kernel<<<(MROWS * M2_ / 4) / 256, 256>>>(out, gamma2, beta2);       // 5
}

// round 13
// speedup vs baseline: 1.4408x; 1.4408x over previous
#include <cuda_runtime.h>
#include <cuda_fp16.h>
#include <cstdint>

// Problem shape (fixed for this instance)
#define B_    16
#define N_    4096
#define S_    1024
#define C2_   256
#define C1_   128
#define CIN_  384      // C2_ + C1_
#define M1_   256
#define M2_   128
#define MROWS (B_ * N_)   // 65536

// ---------------------------------------------------------------------------
// Scratch (static __device__ globals)
// ---------------------------------------------------------------------------
__device__ __half g_xh[(size_t)MROWS * CIN_];   // concat input, fp16
__device__ float  g_y1[(size_t)MROWS * M1_];    // raw conv1 output fp32
__device__ __half g_w1h[M1_ * CIN_];
__device__ __half g_w2h[M2_ * M1_];
__device__ float g_sum1[M1_], g_sq1[M1_];
__device__ float g_sum2[M2_], g_sq2[M2_];

// ---------------------------------------------------------------------------
// PTX helpers — all baseline compute_80-level (no arch-specific features)
// ---------------------------------------------------------------------------
__device__ __forceinline__ unsigned smem_u32(const void* p) {
    unsigned a;
    asm("{ .reg .u64 t; cvta.to.shared.u64 t, %1; cvt.u32.u64 %0, t; }"
        : "=r"(a) : "l"(p));
    return a;
}
__device__ __forceinline__ void cp16(unsigned dst, const void* src) {
    asm volatile("cp.async.cg.shared.global [%0], [%1], 16;"
                 :: "r"(dst), "l"(src) : "memory");
}
__device__ __forceinline__ void cp_commit() {
    asm volatile("cp.async.commit_group;" ::: "memory");
}
template <int N>
__device__ __forceinline__ void cp_wait() {
    asm volatile("cp.async.wait_group %0;" :: "n"(N) : "memory");
}
__device__ __forceinline__ void ldsm4(unsigned* r, unsigned addr) {
    asm volatile("ldmatrix.sync.aligned.m8n8.x4.shared.b16 {%0,%1,%2,%3}, [%4];"
                 : "=r"(r[0]), "=r"(r[1]), "=r"(r[2]), "=r"(r[3]) : "r"(addr));
}
__device__ __forceinline__ void mma16816(float* d, const unsigned* a,
                                         unsigned b0, unsigned b1) {
    asm volatile(
        "mma.sync.aligned.m16n8k16.row.col.f32.f16.f16.f32 "
        "{%0,%1,%2,%3}, {%4,%5,%6,%7}, {%8,%9}, {%0,%1,%2,%3};"
        : "+f"(d[0]), "+f"(d[1]), "+f"(d[2]), "+f"(d[3])
        : "r"(a[0]), "r"(a[1]), "r"(a[2]), "r"(a[3]), "r"(b0), "r"(b1));
}
__device__ __forceinline__ unsigned pack2h(__half lo, __half hi) {
    return ((unsigned)__half_as_ushort(hi) << 16) | (unsigned)__half_as_ushort(lo);
}

// ---------------------------------------------------------------------------
// prep_a: W1 -> fp16                         (launch index 0)
// prep_b: W2 -> fp16 + zero BN stat accums   (launch index 1)
// ---------------------------------------------------------------------------
__global__ void prep_a_kernel(const float* __restrict__ W1) {
    const int idx = blockIdx.x * 256 + threadIdx.x;
    if (idx < M1_ * CIN_) g_w1h[idx] = __float2half(W1[idx]);
}
__global__ void prep_b_kernel(const float* __restrict__ W2) {
    const int idx = blockIdx.x * 256 + threadIdx.x;
    if (blockIdx.x == 0) {
        const int t = threadIdx.x;
        if (t < M1_) { g_sum1[t] = 0.f; g_sq1[t] = 0.f; }
        if (t < M2_) { g_sum2[t] = 0.f; g_sq2[t] = 0.f; }
    }
    if (idx < M2_ * M1_) g_w2h[idx] = __float2half(W2[idx]);
}

// ---------------------------------------------------------------------------
// Kernel: 3-NN interpolation + concat -> fp16 plane g_xh
// ---------------------------------------------------------------------------
__global__ void interp_concat_kernel(const float* __restrict__ txyz,
                                     const float* __restrict__ sxyz,
                                     const float* __restrict__ sfeat,
                                     const float* __restrict__ skip)
{
    __shared__ float4 s_src[S_];
    __shared__ float  s_w[3][128];
    __shared__ int    s_i[3][128];

    const int b   = blockIdx.y;
    const int p0  = blockIdx.x * 128;
    const int tid = threadIdx.x;

    const float* sx = sxyz + (size_t)b * S_ * 3;
    for (int i = tid; i < S_; i += 128) {
        float x = sx[i * 3 + 0], y = sx[i * 3 + 1], z = sx[i * 3 + 2];
        s_src[i] = make_float4(x, y, z, x * x + y * y + z * z);
    }
    __syncthreads();

    const int n = p0 + tid;
    const float* tp = txyz + ((size_t)b * N_ + n) * 3;
    const float tx0 = tp[0], ty0 = tp[1], tz0 = tp[2];
    const float q2 = tx0 * tx0 + ty0 * ty0 + tz0 * tz0;

    float d0 = 3.4e38f, d1 = 3.4e38f, d2 = 3.4e38f;
    int   i0 = 0, i1 = 0, i2 = 0;
    #pragma unroll 4
    for (int s = 0; s < S_; ++s) {
        float4 v = s_src[s];
        float cr   = tx0 * v.x + ty0 * v.y + tz0 * v.z;
        float dist = fmaxf(q2 + v.w - 2.f * cr, 0.f);
        if (dist < d2) {
            if (dist < d1) {
                d2 = d1; i2 = i1;
                if (dist < d0) { d1 = d0; i1 = i0; d0 = dist; i0 = s; }
                else           { d1 = dist; i1 = s; }
            } else { d2 = dist; i2 = s; }
        }
    }

    int   ii[3] = { i0, i1, i2 };
    float w[3];
    float wsum = 0.f;
    #pragma unroll
    for (int k = 0; k < 3; ++k) {
        float4 v = s_src[ii[k]];
        float dx = tx0 - v.x, dy = ty0 - v.y, dz = tz0 - v.z;
        float dd = dx * dx + dy * dy + dz * dz;
        w[k] = 1.f / (dd + 1e-8f);
        wsum += w[k];
    }
    float inv = 1.f / wsum;
    #pragma unroll
    for (int k = 0; k < 3; ++k) { s_w[k][tid] = w[k] * inv; s_i[k][tid] = ii[k]; }
    __syncthreads();

    const float* F = sfeat + (size_t)b * S_ * C2_;
    for (int p = 0; p < 128; ++p) {
        const float w0 = s_w[0][p], w1 = s_w[1][p], w2 = s_w[2][p];
        const float* f0 = F + (size_t)s_i[0][p] * C2_;
        const float* f1 = F + (size_t)s_i[1][p] * C2_;
        const float* f2 = F + (size_t)s_i[2][p] * C2_;
        const size_t row = (size_t)b * N_ + p0 + p;
        __half2* xh2 = (__half2*)(g_xh + row * CIN_);

        {   // interp channels: pair q = tid covers channels 2q, 2q+1 (0..255)
            const int q = tid;
            float2 a  = *(const float2*)(f0 + 2 * q);
            float2 b2 = *(const float2*)(f1 + 2 * q);
            float2 c  = *(const float2*)(f2 + 2 * q);
            float v0 = w0 * a.x + w1 * b2.x + w2 * c.x;
            float v1 = w0 * a.y + w1 * b2.y + w2 * c.y;
            xh2[q] = __floats2half2_rn(v0, v1);
        }
        if (tid < 64) {  // skip channels: pairs 128..191
            float2 sv = *(const float2*)(skip + row * C1_ + 2 * tid);
            xh2[128 + tid] = __floats2half2_rn(sv.x, sv.y);
        }
    }
}

// ---------------------------------------------------------------------------
// mma.sync GEMM (fp16 single-term): C[M,128-tile] = T(A)[M,K] * W[N,K]^T
//   FIRST : A = g_xh fp16 via cp.async (3-stage); C = g_y1; stats1
//   SECOND: A = g_y1 fp32 -> BN1+ReLU -> fp16 in manual producer; C = out; stats2
// Block tile 128x128x32, 256 thr = 8 warps (2 M x 4 N). Rows: 32 fp16 + 16 pad = 80B.
// ---------------------------------------------------------------------------
#define APL_   (128 * 80)            // A plane per stage
#define BPL_   (128 * 80)            // B plane per stage
#define STG_   (APL_ + BPL_)         // 20480
#define REDO_  68608                 // after max(3*STG_=61440, Ct=67584)
#define SCO_   (REDO_ + 1024)
#define SMEMSZ (SCO_ + 2 * M1_ * 4)  // 71680

template <int K, int NOUT, bool SECOND>
__global__ void __launch_bounds__(256, 2)
gemm_mma_kernel(float* __restrict__ outp,
                const float* __restrict__ gamma, const float* __restrict__ beta)
{
    constexpr int NC = K / 32;

    extern __shared__ char sm[];
    const unsigned sb = smem_u32(sm);

    const int tid  = threadIdx.x;
    const int wid  = tid >> 5;
    const int lane = tid & 31;
    const int warpM = wid & 1;
    const int warpN = wid >> 1;
    const int n0 = blockIdx.x * 128;
    const size_t m0 = (size_t)blockIdx.y * 128;

    float* C = SECOND ? outp : g_y1;
    const __half* Wh = SECOND ? g_w2h : g_w1h;
    float* gsum = SECOND ? g_sum2 : g_sum1;
    float* gsq  = SECOND ? g_sq2  : g_sq1;

    float* redsum = (float*)(sm + REDO_);
    float* redsq  = redsum + 128;
    float* s_sc   = (float*)(sm + SCO_);
    float* s_sh   = s_sc + K;

    if (tid < 128) { redsum[tid] = 0.f; redsq[tid] = 0.f; }
    if (SECOND && tid < K) {             // BN1 coefficients from raw sums
        const float invC = 1.0f / (float)MROWS;
        float mean = g_sum1[tid] * invC;
        float var  = g_sq1[tid] * invC - mean * mean;
        float sc   = gamma[tid] * rsqrtf(var + 1e-5f);
        s_sc[tid] = sc;
        s_sh[tid] = fmaf(-mean, sc, beta[tid]);
    }
    __syncthreads();

    // ---- producers -------------------------------------------------------
    auto produceB = [&](int buf) {
        // captured kc via arg below; signature: (buf, kc)
    };
    (void)produceB;
    auto prodB = [&](int buf, int kc) {
        const int r = tid >> 2, c = tid & 3;
        const unsigned bb = sb + buf * STG_ + APL_;
        #pragma unroll
        for (int s = 0; s < 2; ++s) {
            const int row = r + 64 * s;
            const size_t g = (size_t)(n0 + row) * K + kc * 32 + c * 8;
            cp16(bb + row * 80 + c * 16, Wh + g);
        }
    };
    auto prodA1 = [&](int buf, int kc) {          // FIRST: cp.async fp16
        const int r = tid >> 2, c = tid & 3;
        const unsigned ab = sb + buf * STG_;
        #pragma unroll
        for (int s = 0; s < 2; ++s) {
            const int row = r + 64 * s;
            const size_t g = (m0 + row) * CIN_ + kc * 32 + c * 8;
            cp16(ab + row * 80 + c * 16, g_xh + g);
        }
    };
    // SECOND: manual A producer (LDG fp32 -> BN+ReLU -> fp16 STS), 16 vals/thr
    float4 areg[4];
    auto ldA2 = [&](int kc) {
        const int r = tid >> 1, half = tid & 1;
        const float* src = g_y1 + (m0 + r) * K + kc * 32 + half * 16;
        #pragma unroll
        for (int q = 0; q < 4; ++q) areg[q] = *(const float4*)(src + q * 4);
    };
    auto stA2 = [&](int buf, int kc) {
        const int r = tid >> 1, half = tid & 1;
        const int kk = kc * 32 + half * 16;
        unsigned hv[8];
        #pragma unroll
        for (int q = 0; q < 4; ++q) {
            float4 v = areg[q];
            const int kb = kk + q * 4;
            v.x = fmaxf(fmaf(v.x, s_sc[kb + 0], s_sh[kb + 0]), 0.f);
            v.y = fmaxf(fmaf(v.y, s_sc[kb + 1], s_sh[kb + 1]), 0.f);
            v.z = fmaxf(fmaf(v.z, s_sc[kb + 2], s_sh[kb + 2]), 0.f);
            v.w = fmaxf(fmaf(v.w, s_sc[kb + 3], s_sh[kb + 3]), 0.f);
            hv[q * 2 + 0] = pack2h(__float2half(v.x), __float2half(v.y));
            hv[q * 2 + 1] = pack2h(__float2half(v.z), __float2half(v.w));
        }
        char* ad = sm + buf * STG_ + r * 80 + half * 32;
        *(uint4*)(ad)      = make_uint4(hv[0], hv[1], hv[2], hv[3]);
        *(uint4*)(ad + 16) = make_uint4(hv[4], hv[5], hv[6], hv[7]);
    };

    // ---- ldmatrix per-lane base offsets ----------------------------------
    const unsigned aRowOff =
        (unsigned)((warpM * 64 + (lane & 15)) * 80 + ((lane >> 4) & 1) * 16);
    const unsigned bRowOff =
        (unsigned)((warpN * 32 + ((lane >> 4) << 3) + (lane & 7)) * 80 +
                   ((lane >> 3) & 1) * 16);

    float acc[4][4][4];
    #pragma unroll
    for (int i = 0; i < 4; ++i)
        #pragma unroll
        for (int j = 0; j < 4; ++j)
            #pragma unroll
            for (int q = 0; q < 4; ++q) acc[i][j][q] = 0.f;

    // ---- prologue: fill stages 0,1 (one cp group each) -------------------
    if (SECOND) { ldA2(0); stA2(0, 0); }
    else        prodA1(0, 0);
    prodB(0, 0);
    cp_commit();
    if (SECOND) { ldA2(1); stA2(1, 1); }
    else        prodA1(1, 1);
    prodB(1, 1);
    cp_commit();
    if (SECOND && NC > 2) ldA2(2);

    // ---- main loop (3-stage; one commit per iteration, empty ones in tail)
    for (int kc = 0; kc < NC; ++kc) {
        cp_wait<1>();                  // group kc drained (2 outstanding max)
        __syncthreads();
        const int nbuf = (kc + 2) % 3;
        if (kc + 2 < NC) {
            prodB(nbuf, kc + 2);
            if (!SECOND) prodA1(nbuf, kc + 2);
        }
        cp_commit();

        const unsigned base = sb + (kc % 3) * STG_;
        const unsigned aH = base + aRowOff;
        const unsigned bH = base + APL_ + bRowOff;

        #pragma unroll
        for (int k16 = 0; k16 < 2; ++k16) {
            const unsigned ko = k16 * 32;
            unsigned bh[8];
            ldsm4(bh + 0, bH + ko);
            ldsm4(bh + 4, bH + ko + 16 * 80);
            #pragma unroll
            for (int i = 0; i < 4; ++i) {
                unsigned ah[4];
                ldsm4(ah, aH + ko + i * (16 * 80));
                #pragma unroll
                for (int j = 0; j < 4; ++j)
                    mma16816(acc[i][j], ah, bh[2 * j], bh[2 * j + 1]);
            }
        }

        if (SECOND && kc + 2 < NC) {
            stA2(nbuf, kc + 2);                  // LDG latency hidden by MMAs
            if (kc + 3 < NC) ldA2(kc + 3);
        }
    }

    // ---- epilogue: regs -> smem C-tile -> coalesced store + BN stats -----
    __syncthreads();                      // all tile reads done; reuse smem
    float* Ct = (float*)sm;               // 128 x 132 fp32 (67.6 KB, below REDO_)
    const int g = lane >> 2, q = lane & 3;
    #pragma unroll
    for (int i = 0; i < 4; ++i) {
        const int r0 = warpM * 64 + i * 16 + g;
        #pragma unroll
        for (int j = 0; j < 4; ++j) {
            const int c0 = warpN * 32 + j * 8 + q * 2;
            *(float2*)&Ct[r0 * 132 + c0]       = make_float2(acc[i][j][0], acc[i][j][1]);
            *(float2*)&Ct[(r0 + 8) * 132 + c0] = make_float2(acc[i][j][2], acc[i][j][3]);
        }
    }
    __syncthreads();

    float4 s4 = make_float4(0, 0, 0, 0), q4v = make_float4(0, 0, 0, 0);
    const int cc = (tid & 31) * 4;
    #pragma unroll
    for (int p = 0; p < 16; ++p) {
        const int idx = tid + p * 256;
        const int row = idx >> 5;
        float4 v = *(float4*)&Ct[row * 132 + cc];
        *(float4*)(C + (m0 + row) * NOUT + n0 + cc) = v;
        s4.x += v.x; s4.y += v.y; s4.z += v.z; s4.w += v.w;
        q4v.x = fmaf(v.x, v.x, q4v.x); q4v.y = fmaf(v.y, v.y, q4v.y);
        q4v.z = fmaf(v.z, v.z, q4v.z); q4v.w = fmaf(v.w, v.w, q4v.w);
    }
    atomicAdd(&redsum[cc + 0], s4.x); atomicAdd(&redsum[cc + 1], s4.y);
    atomicAdd(&redsum[cc + 2], s4.z); atomicAdd(&redsum[cc + 3], s4.w);
    atomicAdd(&redsq [cc + 0], q4v.x); atomicAdd(&redsq [cc + 1], q4v.y);
    atomicAdd(&redsq [cc + 2], q4v.z); atomicAdd(&redsq [cc + 3], q4v.w);
    __syncthreads();
    if (tid < 128) {
        atomicAdd(&gsum[n0 + tid], redsum[tid]);
        atomicAdd(&gsq [n0 + tid], redsq [tid]);
    }
}

// ---------------------------------------------------------------------------
// final BN2 + ReLU, in-place on d_out [MROWS, 128]; coefs computed per block
// ---------------------------------------------------------------------------
__global__ void bn_out_kernel(float* __restrict__ out,
                              const float* __restrict__ gamma2,
                              const float* __restrict__ beta2)
{
    __shared__ float s2[M2_], t2[M2_];
    const int tid = threadIdx.x;
    if (tid < M2_) {
        const float invC = 1.0f / (float)MROWS;
        float mean = g_sum2[tid] * invC;
        float var  = g_sq2[tid] * invC - mean * mean;
        float sc   = gamma2[tid] * rsqrtf(var + 1e-5f);
        s2[tid] = sc;
        t2[tid] = fmaf(-mean, sc, beta2[tid]);
    }
    __syncthreads();

    const size_t idx = (size_t)blockIdx.x * blockDim.x + tid;  // float4 idx
    float4 v = ((float4*)out)[idx];
    const int c = ((int)(idx * 4)) & (M2_ - 1);
    v.x = fmaxf(fmaf(v.x, s2[c + 0], t2[c + 0]), 0.f);
    v.y = fmaxf(fmaf(v.y, s2[c + 1], t2[c + 1]), 0.f);
    v.z = fmaxf(fmaf(v.z, s2[c + 2], t2[c + 2]), 0.f);
    v.w = fmaxf(fmaf(v.w, s2[c + 3], t2[c + 3]), 0.f);
    ((float4*)out)[idx] = v;
}

// ---------------------------------------------------------------------------
// Launch — GEMM1 at launch index 3 (= ncu's sampled launch)
// ---------------------------------------------------------------------------
extern "C" void kernel_launch(void* const* d_in, const int* in_sizes, int n_in,
                              void* d_out, int out_size)
{
    const float* txyz   = (const float*)d_in[0];
    const float* sxyz   = (const float*)d_in[1];
    const float* sfeat  = (const float*)d_in[2];
    const float* skip   = (const float*)d_in[3];
    const float* W1     = (const float*)d_in[4];
    const float* gamma1 = (const float*)d_in[5];
    const float* beta1  = (const float*)d_in[6];
    const float* W2     = (const float*)d_in[7];
    const float* gamma2 = (const float*)d_in[8];
    const float* beta2  = (const float*)d_in[9];
    float* out = (float*)d_out;

    cudaFuncSetAttribute(gemm_mma_kernel<CIN_, M1_, false>,
                         cudaFuncAttributeMaxDynamicSharedMemorySize, SMEMSZ);
    cudaFuncSetAttribute(gemm_mma_kernel<M1_, M2_, true>,
                         cudaFuncAttributeMaxDynamicSharedMemorySize, SMEMSZ);

    prep_a_kernel<<<(M1_ * CIN_ + 255) / 256, 256>>>(W1);                      // 0
    prep_b_kernel<<<(M2_ * M1_ + 255) / 256, 256>>>(W2);                       // 1
    interp_concat_kernel<<<dim3(N_ / 128, B_), 128>>>(txyz, sxyz, sfeat, skip); // 2
    gemm_mma_kernel<CIN_, M1_, false><<<dim3(M1_ / 128, MROWS / 128), 256, SMEMSZ>>>(
        nullptr, nullptr, nullptr);                                            // 3 <- profiled
    gemm_mma_kernel<M1_, M2_, true><<<dim3(M2_ / 128, MROWS / 128), 256, SMEMSZ>>>(
        out, gamma1, beta1);                                                   // 4
    bn_out_kernel<<<(MROWS * M2_ / 4) / 256, 256>>>(out, gamma2, beta2);       // 5
}